// round 15
// baseline (speedup 1.0000x reference)
#include <cuda_runtime.h>
#include <cuda_fp16.h>
#include <cstdint>

#define D 64
#define MAX_NODES 50000
#define CAP 128            // bucket capacity per node (Poisson(16) degrees)
#define OVF_CAP 4096
#define FILL_BLOCKS 148

// ---- scratch (zero-initialized at load; gather restores zeros each run) ----
__device__ __half   g_support_h[MAX_NODES * D];     // X @ W in fp16 (6.4 MB)
__device__ int      g_cnt[MAX_NODES + 1];           // per-dst counters; [MAX_NODES] = novf
__device__ unsigned g_bucket[MAX_NODES * CAP];      // (fp16 w << 16 | src) per dst (25.6 MB)
__device__ int3     g_ovf[OVF_CAP];                 // (dst, src, fp32 w) spill

// ---------------------------------------------------------------------------
__device__ __forceinline__ void fill_one(int d, int s, float w) {
    int slot = atomicAdd(&g_cnt[d], 1);
    if (slot < CAP) {
        unsigned pk = (unsigned)s |
                      ((unsigned)__half_as_ushort(__float2half_rn(w)) << 16);
        g_bucket[d * CAP + slot] = pk;
    } else {
        int o = atomicAdd(&g_cnt[MAX_NODES], 1);
        if (o < OVF_CAP)
            g_ovf[o] = make_int3(d, s, __float_as_int(w));
    }
}

// ---------------------------------------------------------------------------
// fused: blocks [0, gemm_blocks)  -> HMMA GEMM (support_h = fp16(X @ W))
//        blocks [gemm_blocks, +FILL_BLOCKS) -> bucket fill (grid-stride)
// ---------------------------------------------------------------------------
#define GR 128
#define LDA 72

__device__ __forceinline__ uint32_t smem_u32(const void* p) {
    return static_cast<uint32_t>(__cvta_generic_to_shared(p));
}

__device__ __forceinline__ void ldsm_x4(uint32_t& r0, uint32_t& r1,
                                        uint32_t& r2, uint32_t& r3, uint32_t addr) {
    asm volatile("ldmatrix.sync.aligned.m8n8.x4.shared.b16 {%0,%1,%2,%3}, [%4];"
                 : "=r"(r0), "=r"(r1), "=r"(r2), "=r"(r3) : "r"(addr));
}

__device__ __forceinline__ void ldsm_x2_trans(uint32_t& r0, uint32_t& r1, uint32_t addr) {
    asm volatile("ldmatrix.sync.aligned.m8n8.x2.trans.shared.b16 {%0,%1}, [%2];"
                 : "=r"(r0), "=r"(r1) : "r"(addr));
}

__device__ __forceinline__ void mma_16816(float* c, uint32_t a0, uint32_t a1,
                                          uint32_t a2, uint32_t a3,
                                          uint32_t b0, uint32_t b1) {
    asm volatile(
        "mma.sync.aligned.m16n8k16.row.col.f32.f16.f16.f32 "
        "{%0,%1,%2,%3}, {%4,%5,%6,%7}, {%8,%9}, {%0,%1,%2,%3};"
        : "+f"(c[0]), "+f"(c[1]), "+f"(c[2]), "+f"(c[3])
        : "r"(a0), "r"(a1), "r"(a2), "r"(a3), "r"(b0), "r"(b1));
}

__global__ __launch_bounds__(256) void fused_gemm_fill(
    const float* __restrict__ X, const float* __restrict__ W, int n_nodes,
    const int* __restrict__ edge_src, const int* __restrict__ edge_dst,
    const float* __restrict__ edge_weight, int n_edges, int gemm_blocks) {

    if (blockIdx.x >= gemm_blocks) {
        const int tid0 = (blockIdx.x - gemm_blocks) * blockDim.x + threadIdx.x;
        const int nthr = FILL_BLOCKS * blockDim.x;
        const int half = n_edges >> 1;
        for (int e2 = tid0; e2 < half; e2 += nthr) {
            const int e = e2 * 2;
            int2 d = *reinterpret_cast<const int2*>(edge_dst + e);
            int2 s = *reinterpret_cast<const int2*>(edge_src + e);
            float2 w = *reinterpret_cast<const float2*>(edge_weight + e);
            fill_one(d.x, s.x, w.x);
            fill_one(d.y, s.y, w.y);
        }
        if (tid0 == 0 && (n_edges & 1)) {
            const int e = n_edges - 1;
            fill_one(edge_dst[e], edge_src[e], edge_weight[e]);
        }
        return;
    }

    __shared__ __align__(16) __half sA[GR][LDA];
    __shared__ __align__(16) __half sB[D][LDA];

    const int tid = threadIdx.x;
    const int lane = tid & 31;
    const int warp = tid >> 5;
    const int row0 = blockIdx.x * GR;

    {
        const int r = tid >> 2;
        const int c0 = (tid & 3) * 16;
#pragma unroll
        for (int j = 0; j < 4; j++) {
            float4 v = *reinterpret_cast<const float4*>(W + r * D + c0 + j * 4);
            *reinterpret_cast<__half2*>(&sB[r][c0 + j * 4])     = __floats2half2_rn(v.x, v.y);
            *reinterpret_cast<__half2*>(&sB[r][c0 + j * 4 + 2]) = __floats2half2_rn(v.z, v.w);
        }
    }
    {
        const int r = tid >> 1;
        const int c0 = (tid & 1) * 32;
        const int grow = row0 + r;
#pragma unroll
        for (int j = 0; j < 8; j++) {
            float4 v = make_float4(0.f, 0.f, 0.f, 0.f);
            if (grow < n_nodes)
                v = *reinterpret_cast<const float4*>(X + grow * D + c0 + j * 4);
            *reinterpret_cast<__half2*>(&sA[r][c0 + j * 4])     = __floats2half2_rn(v.x, v.y);
            *reinterpret_cast<__half2*>(&sA[r][c0 + j * 4 + 2]) = __floats2half2_rn(v.z, v.w);
        }
    }
    __syncthreads();

    const int mr = warp * 16;
    const int a_row = mr + (lane & 7) + ((lane & 8) ? 8 : 0);
    const int a_col = (lane & 16) ? 8 : 0;
    const int b_row = (lane & 15);

    float acc[8][4] = {};

#pragma unroll
    for (int ks = 0; ks < 4; ks++) {
        const int k0 = ks * 16;
        uint32_t a0, a1, a2, a3;
        ldsm_x4(a0, a1, a2, a3, smem_u32(&sA[a_row][k0 + a_col]));
#pragma unroll
        for (int n = 0; n < 8; n++) {
            uint32_t b0, b1;
            ldsm_x2_trans(b0, b1, smem_u32(&sB[k0 + b_row][n * 8]));
            mma_16816(acc[n], a0, a1, a2, a3, b0, b1);
        }
    }

    const int g = lane >> 2;
    const int tg = lane & 3;
    const int r0g = row0 + mr + g;
    const int r1g = r0g + 8;
#pragma unroll
    for (int n = 0; n < 8; n++) {
        const int c = n * 8 + tg * 2;
        if (r0g < n_nodes)
            *reinterpret_cast<__half2*>(&g_support_h[r0g * D + c]) =
                __floats2half2_rn(acc[n][0], acc[n][1]);
        if (r1g < n_nodes)
            *reinterpret_cast<__half2*>(&g_support_h[r1g * D + c]) =
                __floats2half2_rn(acc[n][2], acc[n][3]);
    }
}

// ---------------------------------------------------------------------------
// gather: one warp per node, TWO edges in flight (half-warp each).
// NO shfl: each half-warp uniformly loads its packed edge word directly
// (bucket row is contiguous; a 128B line holds 32 edges -> L1 hits).
// Lane owns 4 features (uint2 = 2x half2); flat stride-2 walk, 2-pair unroll.
// Epilogue merges halves with 4 shfl_down(16); lanes 0-15 add bias + store.
// ---------------------------------------------------------------------------
__device__ __forceinline__ void acc_edge2(float* acc, unsigned pk,
                                          const __half* sup, int l16) {
    float w = __half2float(__ushort_as_half((unsigned short)(pk >> 16)));
    uint2 hv = *reinterpret_cast<const uint2*>(
        sup + (pk & 0xFFFFu) * D + l16 * 4);
    float2 v01 = __half22float2(*reinterpret_cast<__half2*>(&hv.x));
    float2 v23 = __half22float2(*reinterpret_cast<__half2*>(&hv.y));
    acc[0] += w * v01.x; acc[1] += w * v01.y;
    acc[2] += w * v23.x; acc[3] += w * v23.y;
}

__global__ __launch_bounds__(256) void gather_kernel(
    const float* __restrict__ b, float* __restrict__ out, int n_nodes) {
    int warp = (blockIdx.x * blockDim.x + threadIdx.x) >> 5;
    int lane = threadIdx.x & 31;
    if (warp >= n_nodes) return;

    const int hw = lane >> 4;        // half-warp id (edge parity)
    const int l16 = lane & 15;       // feature group: owns features [4*l16, +4)

    int deg = g_cnt[warp];
    bool ovfl = deg > CAP;
    if (ovfl) deg = CAP;
    const unsigned* __restrict__ row = &g_bucket[warp * CAP];

    float acc[4] = {};
    const __half* sup = g_support_h;

    // flat walk: this half-warp handles edges hw, hw+2, hw+4, ...
    int j = hw;
    for (; j + 2 < deg; j += 4) {           // 2 edges per half per iter (MLP=2)
        unsigned pk0 = __ldg(&row[j]);
        unsigned pk1 = __ldg(&row[j + 2]);
        acc_edge2(acc, pk0, sup, l16);
        acc_edge2(acc, pk1, sup, l16);
    }
    if (j < deg) {
        unsigned pk = __ldg(&row[j]);
        acc_edge2(acc, pk, sup, l16);
    }

    // merge the two half-warp accumulators onto lanes 0-15
#pragma unroll
    for (int i = 0; i < 4; i++)
        acc[i] += __shfl_down_sync(0xffffffffu, acc[i], 16);

    // overflow path (never taken for this dataset; correct for any input)
    if (ovfl && hw == 0) {
        int novf = g_cnt[MAX_NODES];
        if (novf > OVF_CAP) novf = OVF_CAP;
        for (int o = 0; o < novf; o++) {
            int3 ed = g_ovf[o];
            if (ed.x == warp) {
                float w = __int_as_float(ed.z);
                uint2 hv = *reinterpret_cast<const uint2*>(sup + ed.y * D + l16 * 4);
                float2 v01 = __half22float2(*reinterpret_cast<__half2*>(&hv.x));
                float2 v23 = __half22float2(*reinterpret_cast<__half2*>(&hv.y));
                acc[0] += w * v01.x; acc[1] += w * v01.y;
                acc[2] += w * v23.x; acc[3] += w * v23.y;
            }
        }
    }

    // self-clean for the next replay
    if (lane == 0) g_cnt[warp] = 0;
    if (warp == 0 && lane == 1) g_cnt[MAX_NODES] = 0;

    if (hw == 0) {
        float4 bb = reinterpret_cast<const float4*>(b)[l16];
        float4 r = make_float4(acc[0] + bb.x, acc[1] + bb.y,
                               acc[2] + bb.z, acc[3] + bb.w);
        *reinterpret_cast<float4*>(out + warp * D + l16 * 4) = r;
    }
}

// ---------------------------------------------------------------------------
extern "C" void kernel_launch(void* const* d_in, const int* in_sizes, int n_in,
                              void* d_out, int out_size) {
    const float* X    = (const float*)d_in[0];
    const int*   esrc = (const int*)d_in[1];
    const int*   edst = (const int*)d_in[2];
    const float* ew   = (const float*)d_in[3];
    const float* W    = (const float*)d_in[4];
    const float* b    = (const float*)d_in[5];
    float*       out  = (float*)d_out;

    int n_nodes = in_sizes[0] / D;
    int n_edges = in_sizes[1];
    int gemm_blocks = (n_nodes + GR - 1) / GR;

    fused_gemm_fill<<<gemm_blocks + FILL_BLOCKS, 256>>>(
        X, W, n_nodes, esrc, edst, ew, n_edges, gemm_blocks);
    gather_kernel<<<(n_nodes * 32 + 255) / 256, 256>>>(b, out, n_nodes);
}

// round 16
// speedup vs baseline: 1.0316x; 1.0316x over previous
#include <cuda_runtime.h>
#include <cuda_fp16.h>
#include <cstdint>

#define D 64
#define MAX_NODES 50000
#define CAP 128            // bucket capacity per node (Poisson(16) degrees)
#define OVF_CAP 4096
#define FILL_BLOCKS 148

// ---- scratch (zero-initialized at load; gather restores zeros each run) ----
__device__ float    g_support[MAX_NODES * D];       // X @ W in fp32 (12.8 MB)
__device__ int      g_cnt[MAX_NODES + 1];           // per-dst counters; [MAX_NODES] = novf
__device__ unsigned g_bucket[MAX_NODES * CAP];      // (fp16 w << 16 | src) per dst (25.6 MB)
__device__ int3     g_ovf[OVF_CAP];                 // (dst, src, fp32 w) spill

// ---------------------------------------------------------------------------
__device__ __forceinline__ void fill_one(int d, int s, float w) {
    int slot = atomicAdd(&g_cnt[d], 1);
    if (slot < CAP) {
        unsigned pk = (unsigned)s |
                      ((unsigned)__half_as_ushort(__float2half_rn(w)) << 16);
        g_bucket[d * CAP + slot] = pk;
    } else {
        int o = atomicAdd(&g_cnt[MAX_NODES], 1);
        if (o < OVF_CAP)
            g_ovf[o] = make_int3(d, s, __float_as_int(w));
    }
}

// ---------------------------------------------------------------------------
// fused: blocks [0, gemm_blocks)  -> HMMA GEMM (support = fp32 X @ W)
//        blocks [gemm_blocks, +FILL_BLOCKS) -> bucket fill (grid-stride)
// ---------------------------------------------------------------------------
#define GR 128
#define LDA 72

__device__ __forceinline__ uint32_t smem_u32(const void* p) {
    return static_cast<uint32_t>(__cvta_generic_to_shared(p));
}

__device__ __forceinline__ void ldsm_x4(uint32_t& r0, uint32_t& r1,
                                        uint32_t& r2, uint32_t& r3, uint32_t addr) {
    asm volatile("ldmatrix.sync.aligned.m8n8.x4.shared.b16 {%0,%1,%2,%3}, [%4];"
                 : "=r"(r0), "=r"(r1), "=r"(r2), "=r"(r3) : "r"(addr));
}

__device__ __forceinline__ void ldsm_x2_trans(uint32_t& r0, uint32_t& r1, uint32_t addr) {
    asm volatile("ldmatrix.sync.aligned.m8n8.x2.trans.shared.b16 {%0,%1}, [%2];"
                 : "=r"(r0), "=r"(r1) : "r"(addr));
}

__device__ __forceinline__ void mma_16816(float* c, uint32_t a0, uint32_t a1,
                                          uint32_t a2, uint32_t a3,
                                          uint32_t b0, uint32_t b1) {
    asm volatile(
        "mma.sync.aligned.m16n8k16.row.col.f32.f16.f16.f32 "
        "{%0,%1,%2,%3}, {%4,%5,%6,%7}, {%8,%9}, {%0,%1,%2,%3};"
        : "+f"(c[0]), "+f"(c[1]), "+f"(c[2]), "+f"(c[3])
        : "r"(a0), "r"(a1), "r"(a2), "r"(a3), "r"(b0), "r"(b1));
}

__global__ __launch_bounds__(256) void fused_gemm_fill(
    const float* __restrict__ X, const float* __restrict__ W, int n_nodes,
    const int* __restrict__ edge_src, const int* __restrict__ edge_dst,
    const float* __restrict__ edge_weight, int n_edges, int gemm_blocks) {

    if (blockIdx.x >= gemm_blocks) {
        const int tid0 = (blockIdx.x - gemm_blocks) * blockDim.x + threadIdx.x;
        const int nthr = FILL_BLOCKS * blockDim.x;
        const int half = n_edges >> 1;
        for (int e2 = tid0; e2 < half; e2 += nthr) {
            const int e = e2 * 2;
            int2 d = *reinterpret_cast<const int2*>(edge_dst + e);
            int2 s = *reinterpret_cast<const int2*>(edge_src + e);
            float2 w = *reinterpret_cast<const float2*>(edge_weight + e);
            fill_one(d.x, s.x, w.x);
            fill_one(d.y, s.y, w.y);
        }
        if (tid0 == 0 && (n_edges & 1)) {
            const int e = n_edges - 1;
            fill_one(edge_dst[e], edge_src[e], edge_weight[e]);
        }
        return;
    }

    __shared__ __align__(16) __half sA[GR][LDA];
    __shared__ __align__(16) __half sB[D][LDA];

    const int tid = threadIdx.x;
    const int lane = tid & 31;
    const int warp = tid >> 5;
    const int row0 = blockIdx.x * GR;

    {
        const int r = tid >> 2;
        const int c0 = (tid & 3) * 16;
#pragma unroll
        for (int j = 0; j < 4; j++) {
            float4 v = *reinterpret_cast<const float4*>(W + r * D + c0 + j * 4);
            *reinterpret_cast<__half2*>(&sB[r][c0 + j * 4])     = __floats2half2_rn(v.x, v.y);
            *reinterpret_cast<__half2*>(&sB[r][c0 + j * 4 + 2]) = __floats2half2_rn(v.z, v.w);
        }
    }
    {
        const int r = tid >> 1;
        const int c0 = (tid & 1) * 32;
        const int grow = row0 + r;
#pragma unroll
        for (int j = 0; j < 8; j++) {
            float4 v = make_float4(0.f, 0.f, 0.f, 0.f);
            if (grow < n_nodes)
                v = *reinterpret_cast<const float4*>(X + grow * D + c0 + j * 4);
            *reinterpret_cast<__half2*>(&sA[r][c0 + j * 4])     = __floats2half2_rn(v.x, v.y);
            *reinterpret_cast<__half2*>(&sA[r][c0 + j * 4 + 2]) = __floats2half2_rn(v.z, v.w);
        }
    }
    __syncthreads();

    const int mr = warp * 16;
    const int a_row = mr + (lane & 7) + ((lane & 8) ? 8 : 0);
    const int a_col = (lane & 16) ? 8 : 0;
    const int b_row = (lane & 15);

    float acc[8][4] = {};

#pragma unroll
    for (int ks = 0; ks < 4; ks++) {
        const int k0 = ks * 16;
        uint32_t a0, a1, a2, a3;
        ldsm_x4(a0, a1, a2, a3, smem_u32(&sA[a_row][k0 + a_col]));
#pragma unroll
        for (int n = 0; n < 8; n++) {
            uint32_t b0, b1;
            ldsm_x2_trans(b0, b1, smem_u32(&sB[k0 + b_row][n * 8]));
            mma_16816(acc[n], a0, a1, a2, a3, b0, b1);
        }
    }

    // epilogue: fp32 stores (float2 per c-pair)
    const int g = lane >> 2;
    const int tg = lane & 3;
    const int r0g = row0 + mr + g;
    const int r1g = r0g + 8;
#pragma unroll
    for (int n = 0; n < 8; n++) {
        const int c = n * 8 + tg * 2;
        if (r0g < n_nodes)
            *reinterpret_cast<float2*>(&g_support[r0g * D + c]) =
                make_float2(acc[n][0], acc[n][1]);
        if (r1g < n_nodes)
            *reinterpret_cast<float2*>(&g_support[r1g * D + c]) =
                make_float2(acc[n][2], acc[n][3]);
    }
}

// ---------------------------------------------------------------------------
// gather (R13 structure, fp32 support): one warp per node, TWO edges in
// flight (half-warp each). Edge words batch-loaded coalesced + shfl-spread.
// Lane owns 4 features via one float4 (LDG.128). No h2f conversions.
// Epilogue merges halves with 4 shfl_down(16); lanes 0-15 add bias + store.
// ---------------------------------------------------------------------------
__device__ __forceinline__ void acc_edge4(float* acc, unsigned pk,
                                          const float* sup, int l16) {
    float w = __half2float(__ushort_as_half((unsigned short)(pk >> 16)));
    float4 v = *reinterpret_cast<const float4*>(
        sup + (pk & 0xFFFFu) * D + l16 * 4);
    acc[0] += w * v.x; acc[1] += w * v.y;
    acc[2] += w * v.z; acc[3] += w * v.w;
}

__global__ __launch_bounds__(256) void gather_kernel(
    const float* __restrict__ b, float* __restrict__ out, int n_nodes) {
    int warp = (blockIdx.x * blockDim.x + threadIdx.x) >> 5;
    int lane = threadIdx.x & 31;
    if (warp >= n_nodes) return;

    const int hw = lane >> 4;        // half-warp id (edge parity)
    const int l16 = lane & 15;       // feature group: owns features [4*l16, +4)

    int deg = g_cnt[warp];
    bool ovfl = deg > CAP;
    if (ovfl) deg = CAP;
    const unsigned* __restrict__ row = &g_bucket[warp * CAP];

    float acc[4] = {};
    const float* sup = g_support;

    for (int p = 0; p < deg; p += 32) {
        int m = deg - p; if (m > 32) m = 32;
        unsigned ed = 0;
        if (lane < m) ed = row[p + lane];
        int j = 0;
        // 8 edges per iteration (4 per half-warp)
        for (; j + 8 <= m; j += 8) {
            unsigned pk0 = __shfl_sync(0xffffffffu, ed, j + 0 + hw);
            unsigned pk1 = __shfl_sync(0xffffffffu, ed, j + 2 + hw);
            unsigned pk2 = __shfl_sync(0xffffffffu, ed, j + 4 + hw);
            unsigned pk3 = __shfl_sync(0xffffffffu, ed, j + 6 + hw);
            acc_edge4(acc, pk0, sup, l16);
            acc_edge4(acc, pk1, sup, l16);
            acc_edge4(acc, pk2, sup, l16);
            acc_edge4(acc, pk3, sup, l16);
        }
        // tail: 2 edges per step; idle half carries w=0 (src 0 row, harmless)
        for (; j < m; j += 2) {
            int idx = j + hw;                       // <= 31 always (m <= 32)
            unsigned pk = __shfl_sync(0xffffffffu, ed, idx > 31 ? 31 : idx);
            if (idx >= m) pk = 0;                   // zero weight
            acc_edge4(acc, pk, sup, l16);
        }
    }

    // merge the two half-warp accumulators onto lanes 0-15
#pragma unroll
    for (int i = 0; i < 4; i++)
        acc[i] += __shfl_down_sync(0xffffffffu, acc[i], 16);

    // overflow path (never taken for this dataset; correct for any input)
    if (ovfl && hw == 0) {
        int novf = g_cnt[MAX_NODES];
        if (novf > OVF_CAP) novf = OVF_CAP;
        for (int o = 0; o < novf; o++) {
            int3 ed = g_ovf[o];
            if (ed.x == warp) {
                float w = __int_as_float(ed.z);
                float4 v = *reinterpret_cast<const float4*>(
                    sup + ed.y * D + l16 * 4);
                acc[0] += w * v.x; acc[1] += w * v.y;
                acc[2] += w * v.z; acc[3] += w * v.w;
            }
        }
    }

    // self-clean for the next replay
    if (lane == 0) g_cnt[warp] = 0;
    if (warp == 0 && lane == 1) g_cnt[MAX_NODES] = 0;

    if (hw == 0) {
        float4 bb = reinterpret_cast<const float4*>(b)[l16];
        float4 r = make_float4(acc[0] + bb.x, acc[1] + bb.y,
                               acc[2] + bb.z, acc[3] + bb.w);
        *reinterpret_cast<float4*>(out + warp * D + l16 * 4) = r;
    }
}

// ---------------------------------------------------------------------------
extern "C" void kernel_launch(void* const* d_in, const int* in_sizes, int n_in,
                              void* d_out, int out_size) {
    const float* X    = (const float*)d_in[0];
    const int*   esrc = (const int*)d_in[1];
    const int*   edst = (const int*)d_in[2];
    const float* ew   = (const float*)d_in[3];
    const float* W    = (const float*)d_in[4];
    const float* b    = (const float*)d_in[5];
    float*       out  = (float*)d_out;

    int n_nodes = in_sizes[0] / D;
    int n_edges = in_sizes[1];
    int gemm_blocks = (n_nodes + GR - 1) / GR;

    fused_gemm_fill<<<gemm_blocks + FILL_BLOCKS, 256>>>(
        X, W, n_nodes, esrc, edst, ew, n_edges, gemm_blocks);
    gather_kernel<<<(n_nodes * 32 + 255) / 256, 256>>>(b, out, n_nodes);
}

// round 17
// speedup vs baseline: 1.0801x; 1.0470x over previous
#include <cuda_runtime.h>
#include <cuda_fp16.h>
#include <cstdint>

#define D 64
#define MAX_NODES 50000
#define CAP 128            // bucket capacity per node (Poisson(16) degrees)
#define OVF_CAP 4096
#define FILL_BLOCKS 148

// ---- scratch (zero-initialized at load; gather restores zeros each run) ----
__device__ __half   g_support_h[MAX_NODES * D];     // X @ W in fp16 (6.4 MB)
__device__ int      g_cnt[MAX_NODES + 1];           // per-dst counters; [MAX_NODES] = novf
__device__ unsigned g_bucket[MAX_NODES * CAP];      // (fp16 w << 16 | src) per dst (25.6 MB)
__device__ int3     g_ovf[OVF_CAP];                 // (dst, src, fp32 w) spill

// ---------------------------------------------------------------------------
__device__ __forceinline__ void fill_one(int d, int s, float w) {
    int slot = atomicAdd(&g_cnt[d], 1);
    if (slot < CAP) {
        unsigned pk = (unsigned)s |
                      ((unsigned)__half_as_ushort(__float2half_rn(w)) << 16);
        g_bucket[d * CAP + slot] = pk;
    } else {
        int o = atomicAdd(&g_cnt[MAX_NODES], 1);
        if (o < OVF_CAP)
            g_ovf[o] = make_int3(d, s, __float_as_int(w));
    }
}

// ---------------------------------------------------------------------------
// fused: blocks [0, gemm_blocks)  -> HMMA GEMM (support_h = fp16(X @ W))
//        blocks [gemm_blocks, +FILL_BLOCKS) -> bucket fill (grid-stride)
// ---------------------------------------------------------------------------
#define GR 128
#define LDA 72

__device__ __forceinline__ uint32_t smem_u32(const void* p) {
    return static_cast<uint32_t>(__cvta_generic_to_shared(p));
}

__device__ __forceinline__ void ldsm_x4(uint32_t& r0, uint32_t& r1,
                                        uint32_t& r2, uint32_t& r3, uint32_t addr) {
    asm volatile("ldmatrix.sync.aligned.m8n8.x4.shared.b16 {%0,%1,%2,%3}, [%4];"
                 : "=r"(r0), "=r"(r1), "=r"(r2), "=r"(r3) : "r"(addr));
}

__device__ __forceinline__ void ldsm_x2_trans(uint32_t& r0, uint32_t& r1, uint32_t addr) {
    asm volatile("ldmatrix.sync.aligned.m8n8.x2.trans.shared.b16 {%0,%1}, [%2];"
                 : "=r"(r0), "=r"(r1) : "r"(addr));
}

__device__ __forceinline__ void mma_16816(float* c, uint32_t a0, uint32_t a1,
                                          uint32_t a2, uint32_t a3,
                                          uint32_t b0, uint32_t b1) {
    asm volatile(
        "mma.sync.aligned.m16n8k16.row.col.f32.f16.f16.f32 "
        "{%0,%1,%2,%3}, {%4,%5,%6,%7}, {%8,%9}, {%0,%1,%2,%3};"
        : "+f"(c[0]), "+f"(c[1]), "+f"(c[2]), "+f"(c[3])
        : "r"(a0), "r"(a1), "r"(a2), "r"(a3), "r"(b0), "r"(b1));
}

__global__ __launch_bounds__(256) void fused_gemm_fill(
    const float* __restrict__ X, const float* __restrict__ W, int n_nodes,
    const int* __restrict__ edge_src, const int* __restrict__ edge_dst,
    const float* __restrict__ edge_weight, int n_edges, int gemm_blocks) {

    if (blockIdx.x >= gemm_blocks) {
        const int tid0 = (blockIdx.x - gemm_blocks) * blockDim.x + threadIdx.x;
        const int nthr = FILL_BLOCKS * blockDim.x;
        const int half = n_edges >> 1;
        for (int e2 = tid0; e2 < half; e2 += nthr) {
            const int e = e2 * 2;
            int2 d = *reinterpret_cast<const int2*>(edge_dst + e);
            int2 s = *reinterpret_cast<const int2*>(edge_src + e);
            float2 w = *reinterpret_cast<const float2*>(edge_weight + e);
            fill_one(d.x, s.x, w.x);
            fill_one(d.y, s.y, w.y);
        }
        if (tid0 == 0 && (n_edges & 1)) {
            const int e = n_edges - 1;
            fill_one(edge_dst[e], edge_src[e], edge_weight[e]);
        }
        return;
    }

    __shared__ __align__(16) __half sA[GR][LDA];
    __shared__ __align__(16) __half sB[D][LDA];

    const int tid = threadIdx.x;
    const int lane = tid & 31;
    const int warp = tid >> 5;
    const int row0 = blockIdx.x * GR;

    {
        const int r = tid >> 2;
        const int c0 = (tid & 3) * 16;
#pragma unroll
        for (int j = 0; j < 4; j++) {
            float4 v = *reinterpret_cast<const float4*>(W + r * D + c0 + j * 4);
            *reinterpret_cast<__half2*>(&sB[r][c0 + j * 4])     = __floats2half2_rn(v.x, v.y);
            *reinterpret_cast<__half2*>(&sB[r][c0 + j * 4 + 2]) = __floats2half2_rn(v.z, v.w);
        }
    }
    {
        const int r = tid >> 1;
        const int c0 = (tid & 1) * 32;
        const int grow = row0 + r;
#pragma unroll
        for (int j = 0; j < 8; j++) {
            float4 v = make_float4(0.f, 0.f, 0.f, 0.f);
            if (grow < n_nodes)
                v = *reinterpret_cast<const float4*>(X + grow * D + c0 + j * 4);
            *reinterpret_cast<__half2*>(&sA[r][c0 + j * 4])     = __floats2half2_rn(v.x, v.y);
            *reinterpret_cast<__half2*>(&sA[r][c0 + j * 4 + 2]) = __floats2half2_rn(v.z, v.w);
        }
    }
    __syncthreads();

    const int mr = warp * 16;
    const int a_row = mr + (lane & 7) + ((lane & 8) ? 8 : 0);
    const int a_col = (lane & 16) ? 8 : 0;
    const int b_row = (lane & 15);

    float acc[8][4] = {};

#pragma unroll
    for (int ks = 0; ks < 4; ks++) {
        const int k0 = ks * 16;
        uint32_t a0, a1, a2, a3;
        ldsm_x4(a0, a1, a2, a3, smem_u32(&sA[a_row][k0 + a_col]));
#pragma unroll
        for (int n = 0; n < 8; n++) {
            uint32_t b0, b1;
            ldsm_x2_trans(b0, b1, smem_u32(&sB[k0 + b_row][n * 8]));
            mma_16816(acc[n], a0, a1, a2, a3, b0, b1);
        }
    }

    const int g = lane >> 2;
    const int tg = lane & 3;
    const int r0g = row0 + mr + g;
    const int r1g = r0g + 8;
#pragma unroll
    for (int n = 0; n < 8; n++) {
        const int c = n * 8 + tg * 2;
        if (r0g < n_nodes)
            *reinterpret_cast<__half2*>(&g_support_h[r0g * D + c]) =
                __floats2half2_rn(acc[n][0], acc[n][1]);
        if (r1g < n_nodes)
            *reinterpret_cast<__half2*>(&g_support_h[r1g * D + c]) =
                __floats2half2_rn(acc[n][2], acc[n][3]);
    }
}

// ---------------------------------------------------------------------------
// gather (R13 shape, MLP widened 4->8): one warp per node, TWO edges in
// flight per instruction (half-warp each), 16 edges per inner iteration
// (8 per half-warp, all loads independent). Lane owns 4 features (uint2).
// Epilogue merges halves with 4 shfl_down(16); lanes 0-15 add bias + store.
// ---------------------------------------------------------------------------
__device__ __forceinline__ void acc_edge2(float* acc, unsigned pk,
                                          const __half* sup, int l16) {
    float w = __half2float(__ushort_as_half((unsigned short)(pk >> 16)));
    uint2 hv = *reinterpret_cast<const uint2*>(
        sup + (pk & 0xFFFFu) * D + l16 * 4);
    float2 v01 = __half22float2(*reinterpret_cast<__half2*>(&hv.x));
    float2 v23 = __half22float2(*reinterpret_cast<__half2*>(&hv.y));
    acc[0] += w * v01.x; acc[1] += w * v01.y;
    acc[2] += w * v23.x; acc[3] += w * v23.y;
}

__global__ __launch_bounds__(256) void gather_kernel(
    const float* __restrict__ b, float* __restrict__ out, int n_nodes) {
    int warp = (blockIdx.x * blockDim.x + threadIdx.x) >> 5;
    int lane = threadIdx.x & 31;
    if (warp >= n_nodes) return;

    const int hw = lane >> 4;        // half-warp id (edge parity)
    const int l16 = lane & 15;       // feature group: owns features [4*l16, +4)

    int deg = g_cnt[warp];
    bool ovfl = deg > CAP;
    if (ovfl) deg = CAP;
    const unsigned* __restrict__ row = &g_bucket[warp * CAP];

    float acc[4] = {};
    const __half* sup = g_support_h;

    for (int p = 0; p < deg; p += 32) {
        int m = deg - p; if (m > 32) m = 32;
        unsigned ed = 0;
        if (lane < m) ed = row[p + lane];
        int j = 0;
        // 16 edges per iteration (8 per half-warp): all shfls, then all loads
        // hoisted -> MLP=8 independent LDG.64 per half-warp.
        for (; j + 16 <= m; j += 16) {
            unsigned pk[8];
#pragma unroll
            for (int q = 0; q < 8; q++)
                pk[q] = __shfl_sync(0xffffffffu, ed, j + 2 * q + hw);
            uint2 hv[8];
#pragma unroll
            for (int q = 0; q < 8; q++)
                hv[q] = *reinterpret_cast<const uint2*>(
                    sup + (pk[q] & 0xFFFFu) * D + l16 * 4);
#pragma unroll
            for (int q = 0; q < 8; q++) {
                float w = __half2float(__ushort_as_half((unsigned short)(pk[q] >> 16)));
                float2 v01 = __half22float2(*reinterpret_cast<__half2*>(&hv[q].x));
                float2 v23 = __half22float2(*reinterpret_cast<__half2*>(&hv[q].y));
                acc[0] += w * v01.x; acc[1] += w * v01.y;
                acc[2] += w * v23.x; acc[3] += w * v23.y;
            }
        }
        // 8-edge step (4 per half-warp)
        for (; j + 8 <= m; j += 8) {
            unsigned pk0 = __shfl_sync(0xffffffffu, ed, j + 0 + hw);
            unsigned pk1 = __shfl_sync(0xffffffffu, ed, j + 2 + hw);
            unsigned pk2 = __shfl_sync(0xffffffffu, ed, j + 4 + hw);
            unsigned pk3 = __shfl_sync(0xffffffffu, ed, j + 6 + hw);
            acc_edge2(acc, pk0, sup, l16);
            acc_edge2(acc, pk1, sup, l16);
            acc_edge2(acc, pk2, sup, l16);
            acc_edge2(acc, pk3, sup, l16);
        }
        // tail: 2 edges per step; idle half carries w=0 (src 0 row, harmless)
        for (; j < m; j += 2) {
            int idx = j + hw;                       // <= 31 always (m <= 32)
            unsigned pk = __shfl_sync(0xffffffffu, ed, idx > 31 ? 31 : idx);
            if (idx >= m) pk = 0;                   // zero weight
            acc_edge2(acc, pk, sup, l16);
        }
    }

    // merge the two half-warp accumulators onto lanes 0-15
#pragma unroll
    for (int i = 0; i < 4; i++)
        acc[i] += __shfl_down_sync(0xffffffffu, acc[i], 16);

    // overflow path (never taken for this dataset; correct for any input)
    if (ovfl && hw == 0) {
        int novf = g_cnt[MAX_NODES];
        if (novf > OVF_CAP) novf = OVF_CAP;
        for (int o = 0; o < novf; o++) {
            int3 ed = g_ovf[o];
            if (ed.x == warp) {
                float w = __int_as_float(ed.z);
                uint2 hv = *reinterpret_cast<const uint2*>(sup + ed.y * D + l16 * 4);
                float2 v01 = __half22float2(*reinterpret_cast<__half2*>(&hv.x));
                float2 v23 = __half22float2(*reinterpret_cast<__half2*>(&hv.y));
                acc[0] += w * v01.x; acc[1] += w * v01.y;
                acc[2] += w * v23.x; acc[3] += w * v23.y;
            }
        }
    }

    // self-clean for the next replay
    if (lane == 0) g_cnt[warp] = 0;
    if (warp == 0 && lane == 1) g_cnt[MAX_NODES] = 0;

    if (hw == 0) {
        float4 bb = reinterpret_cast<const float4*>(b)[l16];
        float4 r = make_float4(acc[0] + bb.x, acc[1] + bb.y,
                               acc[2] + bb.z, acc[3] + bb.w);
        *reinterpret_cast<float4*>(out + warp * D + l16 * 4) = r;
    }
}

// ---------------------------------------------------------------------------
extern "C" void kernel_launch(void* const* d_in, const int* in_sizes, int n_in,
                              void* d_out, int out_size) {
    const float* X    = (const float*)d_in[0];
    const int*   esrc = (const int*)d_in[1];
    const int*   edst = (const int*)d_in[2];
    const float* ew   = (const float*)d_in[3];
    const float* W    = (const float*)d_in[4];
    const float* b    = (const float*)d_in[5];
    float*       out  = (float*)d_out;

    int n_nodes = in_sizes[0] / D;
    int n_edges = in_sizes[1];
    int gemm_blocks = (n_nodes + GR - 1) / GR;

    fused_gemm_fill<<<gemm_blocks + FILL_BLOCKS, 256>>>(
        X, W, n_nodes, esrc, edst, ew, n_edges, gemm_blocks);
    gather_kernel<<<(n_nodes * 32 + 255) / 256, 256>>>(b, out, n_nodes);
}